// round 8
// baseline (speedup 1.0000x reference)
#include <cuda_runtime.h>
#include <math.h>
#include <stdint.h>

#define BB 4
#define SS 4096
#define HH 128
#define ROWS_TOTAL (BB * SS)
#define TK 64            // keys per inner tile

// Scratch (allocation-free path). Q pre-scaled by 1/sqrt(H), all tf32-rounded.
// V stored transposed: g_Vt[b][h][s].
__device__ float g_Q[ROWS_TOTAL * HH];
__device__ float g_K[ROWS_TOTAL * HH];
__device__ float g_Vt[BB * HH * SS];

__device__ __forceinline__ float to_tf32(float x) {
    uint32_t u;
    asm("cvt.rna.tf32.f32 %0, %1;" : "=r"(u) : "f"(x));
    return __uint_as_float(u);
}

__device__ __forceinline__ uint32_t smem_u32_of(const void* p) {
    uint32_t a;
    asm("{ .reg .u64 t; cvta.to.shared.u64 t, %1; cvt.u32.u64 %0, t; }" : "=r"(a) : "l"(p));
    return a;
}

__device__ __forceinline__ void cp_async16(uint32_t dst, const float* src) {
    asm volatile("cp.async.cg.shared.global [%0], [%1], 16;" :: "r"(dst), "l"(src));
}
#define CP_COMMIT() asm volatile("cp.async.commit_group;" ::: "memory")
#define CP_WAIT0()  asm volatile("cp.async.wait_group 0;" ::: "memory")

// m16n8k8 tf32 MMA, D accumulates in place. (Fragment mapping validated R3/R5.)
__device__ __forceinline__ void mma_tf32(float* d, const uint32_t* a,
                                         uint32_t b0, uint32_t b1) {
    asm volatile(
        "mma.sync.aligned.m16n8k8.row.col.f32.tf32.tf32.f32 "
        "{%0,%1,%2,%3}, {%4,%5,%6,%7}, {%8,%9}, {%0,%1,%2,%3};"
        : "+f"(d[0]), "+f"(d[1]), "+f"(d[2]), "+f"(d[3])
        : "r"(a[0]), "r"(a[1]), "r"(a[2]), "r"(a[3]), "r"(b0), "r"(b1));
}

// ---------------------------------------------------------------------------
// Kernel 1: QKV projection via mma.sync tf32 (validated R7, ~4 us).
// Grid (128 row-tiles, 3 chunks). chunk 0 -> Q (scaled), 1 -> K, 2 -> V^T.
// ---------------------------------------------------------------------------
#define QO_W 16384
#define QO_B 32768
#define SMEM_QKV ((32768 + 128) * 4)

__global__ __launch_bounds__(256, 1) void qkv_mma(const float* __restrict__ X,
                                                  const float* __restrict__ W,
                                                  const float* __restrict__ bias)
{
    extern __shared__ float sm[];
    float* Xs = sm;
    float* Ws = sm + QO_W;
    float* Bs = sm + QO_B;

    const int tid = threadIdx.x;
    const int wid = tid >> 5;
    const int lane = tid & 31;
    const int g = lane >> 2;
    const int tg = lane & 3;
    const int xg = g << 2;
    const int m0 = (wid >> 1) * 32;
    const int n0 = (wid & 1) * 64;
    const int row0 = blockIdx.x * 128;
    const int c = blockIdx.y;

    {
        const float4* Xg = (const float4*)(X + (size_t)row0 * HH);
        #pragma unroll
        for (int i = 0; i < 16; i++) {
            int idx = tid + i * 256;
            int r = idx >> 5;
            int c4 = (idx & 31) << 2;
            float4 v = Xg[idx];
            v.x = to_tf32(v.x); v.y = to_tf32(v.y);
            v.z = to_tf32(v.z); v.w = to_tf32(v.w);
            *(float4*)(Xs + (r << 7) + (c4 ^ ((r & 7) << 2))) = v;
        }
        const float4* Wg = (const float4*)(W + (size_t)c * 128 * HH);
        #pragma unroll
        for (int i = 0; i < 16; i++) {
            int idx = tid + i * 256;
            int r = idx >> 5;
            int c4 = (idx & 31) << 2;
            float4 v = Wg[idx];
            v.x = to_tf32(v.x); v.y = to_tf32(v.y);
            v.z = to_tf32(v.z); v.w = to_tf32(v.w);
            *(float4*)(Ws + (r << 7) + (c4 ^ ((r & 7) << 2))) = v;
        }
        if (tid < 128) Bs[tid] = bias[c * 128 + tid];
    }
    __syncthreads();

    float acc[2][8][4];
    #pragma unroll
    for (int st = 0; st < 2; st++)
        #pragma unroll
        for (int nt = 0; nt < 8; nt++)
            #pragma unroll
            for (int j = 0; j < 4; j++) acc[st][nt][j] = 0.0f;

    const float* XA0 = Xs + ((m0 + g) << 7);
    const float* XA1 = Xs + ((m0 + 8 + g) << 7);
    const float* XA2 = Xs + ((m0 + 16 + g) << 7);
    const float* XA3 = Xs + ((m0 + 24 + g) << 7);

    #pragma unroll 2
    for (int ks = 0; ks < 16; ks++) {
        const int k0 = ks * 8;
        const int c0 = (k0 + tg) ^ xg;
        const int c1 = (k0 + tg + 4) ^ xg;
        uint32_t a0[4], a1[4];
        a0[0] = __float_as_uint(XA0[c0]);
        a0[1] = __float_as_uint(XA1[c0]);
        a0[2] = __float_as_uint(XA0[c1]);
        a0[3] = __float_as_uint(XA1[c1]);
        a1[0] = __float_as_uint(XA2[c0]);
        a1[1] = __float_as_uint(XA3[c0]);
        a1[2] = __float_as_uint(XA2[c1]);
        a1[3] = __float_as_uint(XA3[c1]);
        #pragma unroll
        for (int nt = 0; nt < 8; nt++) {
            const float* Br = Ws + ((n0 + nt * 8 + g) << 7);
            uint32_t b0 = __float_as_uint(Br[c0]);
            uint32_t b1 = __float_as_uint(Br[c1]);
            mma_tf32(acc[0][nt], a0, b0, b1);
            mma_tf32(acc[1][nt], a1, b0, b1);
        }
    }

    if (c == 2) {
        __syncthreads();
        float* St = sm;    // 128 x 130 plain (s rows, h cols)
        #pragma unroll
        for (int st = 0; st < 2; st++) {
            #pragma unroll
            for (int nt = 0; nt < 8; nt++) {
                int col = n0 + nt * 8 + 2 * tg;
                int r0 = m0 + 16 * st + g;
                int r1 = r0 + 8;
                float b0v = Bs[col], b1v = Bs[col + 1];
                St[r0 * 130 + col]     = to_tf32(acc[st][nt][0] + b0v);
                St[r0 * 130 + col + 1] = to_tf32(acc[st][nt][1] + b1v);
                St[r1 * 130 + col]     = to_tf32(acc[st][nt][2] + b0v);
                St[r1 * 130 + col + 1] = to_tf32(acc[st][nt][3] + b1v);
            }
        }
        __syncthreads();
        const int b = row0 >> 12;
        const int sbase = row0 & 4095;
        #pragma unroll 4
        for (int i = 0; i < 64; i++) {
            int idx = tid + i * 256;
            int h = idx >> 7;
            int s = idx & 127;
            g_Vt[((size_t)(b * HH + h)) * SS + sbase + s] = St[s * 130 + h];
        }
    } else {
        float* dst = (c == 0 ? g_Q : g_K) + (size_t)row0 * HH;
        const float scale = (c == 0) ? 0.08838834764831845f : 1.0f;
        #pragma unroll
        for (int st = 0; st < 2; st++) {
            #pragma unroll
            for (int nt = 0; nt < 8; nt++) {
                int col = n0 + nt * 8 + 2 * tg;
                int r0 = m0 + 16 * st + g;
                int r1 = r0 + 8;
                float b0v = Bs[col], b1v = Bs[col + 1];
                *(float2*)(dst + (size_t)r0 * HH + col) =
                    make_float2(to_tf32((acc[st][nt][0] + b0v) * scale),
                                to_tf32((acc[st][nt][1] + b1v) * scale));
                *(float2*)(dst + (size_t)r1 * HH + col) =
                    make_float2(to_tf32((acc[st][nt][2] + b0v) * scale),
                                to_tf32((acc[st][nt][3] + b1v) * scale));
            }
        }
    }
}

// ---------------------------------------------------------------------------
// Kernel 2: flash attention, mma.sync tf32, 512 threads (16 warps, 4/SMSP).
// Warp w: m-strip = (w>>2)*32, n-quarter = w&3 (S: 16 keys, PV: 32 head dims).
// cp.async double-buffered key-tiles of 64. Per-strip named barrier (128 thr).
// SMEM (floats): Qs 128x128 | Ks[2] 64x128 | Vs[2] 128x64 | Ps 128x64.
// All tiles XOR-swizzled: col ^ 4*(row&7).
// ---------------------------------------------------------------------------
#define O_Q  0
#define O_K0 16384
#define O_K1 24576
#define O_V0 32768
#define O_V1 40960
#define O_P  49152
#define SMEM_ATTN (57344 * 4)   // 229376 B

__global__ __launch_bounds__(512, 1) void attn_kernel(float* __restrict__ out)
{
    extern __shared__ float sm[];
    const uint32_t smem_u32 = smem_u32_of(sm);
    float* Qs = sm + O_Q;
    float* Ps = sm + O_P;

    const int tid = threadIdx.x;
    const int wid = tid >> 5;
    const int lane = tid & 31;
    const int g = lane >> 2;
    const int tg = lane & 3;
    const int xg = g << 2;
    const int m0 = (wid >> 2) * 32;       // m-strip base (4 strips)
    const int nq = wid & 3;               // n-quarter
    const int n0s = nq * 16;              // S: 16 keys per warp
    const int n0p = nq * 32;              // PV: 32 head dims per warp
    const int strip_bar = 1 + (wid >> 2); // named barrier per strip (128 thr)
    const int b = blockIdx.y;
    const int q0 = blockIdx.x * 128;

    // ---- prologue: cp.async stage tile 0 into buffer 0 ----
    {
        const float* Kg = g_K + ((size_t)b * SS) * HH;
        #pragma unroll
        for (int i = 0; i < 4; i++) {
            int idx = tid + i * 512;
            int r = idx >> 5;
            int c4 = (idx & 31) << 2;
            cp_async16(smem_u32 + (O_K0 + (r << 7) + (c4 ^ ((r & 7) << 2))) * 4,
                       Kg + (r << 7) + c4);
        }
        const float* Vg = g_Vt + (size_t)(b * HH) * SS;
        #pragma unroll
        for (int i = 0; i < 4; i++) {
            int idx = tid + i * 512;
            int h = idx >> 4;
            int c4 = (idx & 15) << 2;
            cp_async16(smem_u32 + (O_V0 + (h << 6) + (c4 ^ ((h & 7) << 2))) * 4,
                       Vg + (size_t)h * SS + c4);
        }
        CP_COMMIT();
    }

    // Load Q tile -> smem (swizzled)
    {
        const float4* Qg = (const float4*)(g_Q + ((size_t)b * SS + q0) * HH);
        #pragma unroll
        for (int i = 0; i < 8; i++) {
            int idx = tid + i * 512;
            int r = idx >> 5;
            int c4 = (idx & 31) << 2;
            *(float4*)(Qs + (r << 7) + (c4 ^ ((r & 7) << 2))) = Qg[idx];
        }
    }

    float oacc[2][4][4];
    #pragma unroll
    for (int st = 0; st < 2; st++)
        #pragma unroll
        for (int nt = 0; nt < 4; nt++)
            #pragma unroll
            for (int j = 0; j < 4; j++) oacc[st][nt][j] = 0.0f;
    float lsum[4] = {0.0f, 0.0f, 0.0f, 0.0f};

    // Fragment row pointers (rows all have row&7 == g -> swizzle xor = xg)
    const float* QA0 = Qs + ((m0 + g) << 7);
    const float* QA1 = Qs + ((m0 + 8 + g) << 7);
    const float* QA2 = Qs + ((m0 + 16 + g) << 7);
    const float* QA3 = Qs + ((m0 + 24 + g) << 7);
    float* PW0 = Ps + ((m0 + g) << 6);
    float* PW1 = Ps + ((m0 + 8 + g) << 6);
    float* PW2 = Ps + ((m0 + 16 + g) << 6);
    float* PW3 = Ps + ((m0 + 24 + g) << 6);

    for (int t = 0; t < 64; t++) {
        const int buf = t & 1;
        const float* Kb = sm + (buf ? O_K1 : O_K0);
        const float* Vb = sm + (buf ? O_V1 : O_V0);

        CP_WAIT0();
        __syncthreads();   // [B] tile t visible; tile t-1 reads fully retired

        // Prefetch tile t+1 into the other buffer
        if (t + 1 < 64) {
            const int obuf_k = buf ? O_K0 : O_K1;
            const int obuf_v = buf ? O_V0 : O_V1;
            const float* Kg = g_K + ((size_t)b * SS + (t + 1) * TK) * HH;
            #pragma unroll
            for (int i = 0; i < 4; i++) {
                int idx = tid + i * 512;
                int r = idx >> 5;
                int c4 = (idx & 31) << 2;
                cp_async16(smem_u32 + (obuf_k + (r << 7) + (c4 ^ ((r & 7) << 2))) * 4,
                           Kg + (r << 7) + c4);
            }
            const float* Vg = g_Vt + (size_t)(b * HH) * SS + (t + 1) * TK;
            #pragma unroll
            for (int i = 0; i < 4; i++) {
                int idx = tid + i * 512;
                int h = idx >> 4;
                int c4 = (idx & 15) << 2;
                cp_async16(smem_u32 + (obuf_v + (h << 6) + (c4 ^ ((h & 7) << 2))) * 4,
                           Vg + (size_t)h * SS + c4);
            }
            CP_COMMIT();
        }

        // --- S = Q . K^T : warp tile m32 x n16 x k128 ---
        float sacc[2][2][4];
        #pragma unroll
        for (int st = 0; st < 2; st++)
            #pragma unroll
            for (int nt = 0; nt < 2; nt++)
                #pragma unroll
                for (int j = 0; j < 4; j++) sacc[st][nt][j] = 0.0f;

        #pragma unroll 4
        for (int ks = 0; ks < 16; ks++) {
            const int k0 = ks * 8;
            const int c0 = (k0 + tg) ^ xg;
            const int c1 = (k0 + tg + 4) ^ xg;
            uint32_t a0[4], a1[4];
            a0[0] = __float_as_uint(QA0[c0]);
            a0[1] = __float_as_uint(QA1[c0]);
            a0[2] = __float_as_uint(QA0[c1]);
            a0[3] = __float_as_uint(QA1[c1]);
            a1[0] = __float_as_uint(QA2[c0]);
            a1[1] = __float_as_uint(QA3[c0]);
            a1[2] = __float_as_uint(QA2[c1]);
            a1[3] = __float_as_uint(QA3[c1]);
            #pragma unroll
            for (int nt = 0; nt < 2; nt++) {
                const float* Br = Kb + ((n0s + nt * 8 + g) << 7);
                uint32_t b0 = __float_as_uint(Br[c0]);
                uint32_t b1 = __float_as_uint(Br[c1]);
                mma_tf32(sacc[0][nt], a0, b0, b1);
                mma_tf32(sacc[1][nt], a1, b0, b1);
            }
        }

        // --- exp + partial row sums + write P (tf32, swizzled 64-wide) ---
        {
            float ps0 = 0.0f, ps1 = 0.0f, ps2 = 0.0f, ps3 = 0.0f;
            #pragma unroll
            for (int nt = 0; nt < 2; nt++) {
                int colp = (n0s + nt * 8 + 2 * tg) ^ xg;
                float e0 = __expf(sacc[0][nt][0]);
                float e1 = __expf(sacc[0][nt][1]);
                float e2 = __expf(sacc[0][nt][2]);
                float e3 = __expf(sacc[0][nt][3]);
                ps0 += e0 + e1; ps1 += e2 + e3;
                *(float2*)(PW0 + colp) = make_float2(to_tf32(e0), to_tf32(e1));
                *(float2*)(PW1 + colp) = make_float2(to_tf32(e2), to_tf32(e3));
                float f0 = __expf(sacc[1][nt][0]);
                float f1 = __expf(sacc[1][nt][1]);
                float f2 = __expf(sacc[1][nt][2]);
                float f3 = __expf(sacc[1][nt][3]);
                ps2 += f0 + f1; ps3 += f2 + f3;
                *(float2*)(PW2 + colp) = make_float2(to_tf32(f0), to_tf32(f1));
                *(float2*)(PW3 + colp) = make_float2(to_tf32(f2), to_tf32(f3));
            }
            ps0 += __shfl_xor_sync(0xffffffffu, ps0, 1);
            ps0 += __shfl_xor_sync(0xffffffffu, ps0, 2);
            ps1 += __shfl_xor_sync(0xffffffffu, ps1, 1);
            ps1 += __shfl_xor_sync(0xffffffffu, ps1, 2);
            ps2 += __shfl_xor_sync(0xffffffffu, ps2, 1);
            ps2 += __shfl_xor_sync(0xffffffffu, ps2, 2);
            ps3 += __shfl_xor_sync(0xffffffffu, ps3, 1);
            ps3 += __shfl_xor_sync(0xffffffffu, ps3, 2);
            lsum[0] += ps0; lsum[1] += ps1; lsum[2] += ps2; lsum[3] += ps3;
        }
        // Strip barrier: 4 warps of this m-strip exchange P rows
        asm volatile("bar.sync %0, 128;" :: "r"(strip_bar) : "memory");

        // --- O += P . V : warp tile m32 x h32 x k64 ---
        #pragma unroll 2
        for (int ks = 0; ks < 8; ks++) {
            const int k0 = ks * 8;
            const int c0 = (k0 + tg) ^ xg;
            const int c1 = (k0 + tg + 4) ^ xg;
            uint32_t a0[4], a1[4];
            a0[0] = __float_as_uint(PW0[c0]);
            a0[1] = __float_as_uint(PW1[c0]);
            a0[2] = __float_as_uint(PW0[c1]);
            a0[3] = __float_as_uint(PW1[c1]);
            a1[0] = __float_as_uint(PW2[c0]);
            a1[1] = __float_as_uint(PW3[c0]);
            a1[2] = __float_as_uint(PW2[c1]);
            a1[3] = __float_as_uint(PW3[c1]);
            #pragma unroll
            for (int nt = 0; nt < 4; nt++) {
                const float* Br = Vb + ((n0p + nt * 8 + g) << 6);
                uint32_t b0 = __float_as_uint(Br[c0]);
                uint32_t b1 = __float_as_uint(Br[c1]);
                mma_tf32(oacc[0][nt], a0, b0, b1);
                mma_tf32(oacc[1][nt], a1, b0, b1);
            }
        }
    }

    // --- Combine per-quarter row sums via smem (reuse Ps region, plain) ---
    __syncthreads();
    {
        float* LS = Ps + nq * 128;
        if (tg == 0) {
            LS[m0 + g] = lsum[0];
            LS[m0 + 8 + g] = lsum[1];
            LS[m0 + 16 + g] = lsum[2];
            LS[m0 + 24 + g] = lsum[3];
        }
    }
    __syncthreads();

    // --- Epilogue: O / l -> gmem ---
    {
        float* og = out + ((size_t)(b * SS) + q0) * HH + n0p;
        #pragma unroll
        for (int st = 0; st < 2; st++) {
            int r0 = m0 + 16 * st + g;
            int r1 = r0 + 8;
            float inv0 = 1.0f / (Ps[r0] + Ps[128 + r0] + Ps[256 + r0] + Ps[384 + r0]);
            float inv1 = 1.0f / (Ps[r1] + Ps[128 + r1] + Ps[256 + r1] + Ps[384 + r1]);
            float* o0 = og + (size_t)r0 * HH;
            float* o1 = og + (size_t)r1 * HH;
            #pragma unroll
            for (int nt = 0; nt < 4; nt++) {
                int col = nt * 8 + 2 * tg;
                *(float2*)(o0 + col) =
                    make_float2(oacc[st][nt][0] * inv0, oacc[st][nt][1] * inv0);
                *(float2*)(o1 + col) =
                    make_float2(oacc[st][nt][2] * inv1, oacc[st][nt][3] * inv1);
            }
        }
    }
}

// ---------------------------------------------------------------------------
extern "C" void kernel_launch(void* const* d_in, const int* in_sizes, int n_in,
                              void* d_out, int out_size)
{
    const float* X    = (const float*)d_in[0];   // [4,4096,128]
    const float* W    = (const float*)d_in[1];   // [384,128]
    const float* bias = (const float*)d_in[2];   // [384]
    float* out = (float*)d_out;                  // [4,4096,128]

    cudaFuncSetAttribute(qkv_mma, cudaFuncAttributeMaxDynamicSharedMemorySize, SMEM_QKV);
    cudaFuncSetAttribute(attn_kernel, cudaFuncAttributeMaxDynamicSharedMemorySize, SMEM_ATTN);

    qkv_mma<<<dim3(128, 3), 256, SMEM_QKV>>>(X, W, bias);
    attn_kernel<<<dim3(SS / 128, BB), 512, SMEM_ATTN>>>(out);
}

// round 9
// speedup vs baseline: 1.9670x; 1.9670x over previous
#include <cuda_runtime.h>
#include <cuda_fp16.h>
#include <math.h>
#include <stdint.h>

#define BB 4
#define SS 4096
#define HH 128
#define ROWS_TOTAL (BB * SS)

// Scratch (allocation-free path). Q pre-scaled by 1/sqrt(H). All fp16.
// V stored transposed: g_Vt[b][h][s].
__device__ __half g_Q[ROWS_TOTAL * HH];
__device__ __half g_K[ROWS_TOTAL * HH];
__device__ __half g_Vt[BB * HH * SS];

__device__ __forceinline__ float to_tf32(float x) {
    uint32_t u;
    asm("cvt.rna.tf32.f32 %0, %1;" : "=r"(u) : "f"(x));
    return __uint_as_float(u);
}

__device__ __forceinline__ uint32_t smem_u32_of(const void* p) {
    uint32_t a;
    asm("{ .reg .u64 t; cvta.to.shared.u64 t, %1; cvt.u32.u64 %0, t; }" : "=r"(a) : "l"(p));
    return a;
}

__device__ __forceinline__ void cp_async16(uint32_t dst, const void* src) {
    asm volatile("cp.async.cg.shared.global [%0], [%1], 16;" :: "r"(dst), "l"(src));
}
#define CP_COMMIT() asm volatile("cp.async.commit_group;" ::: "memory")
#define CP_WAIT0()  asm volatile("cp.async.wait_group 0;" ::: "memory")

// tf32 m16n8k8 (for QKV projection; validated R3-R8)
__device__ __forceinline__ void mma_tf32(float* d, const uint32_t* a,
                                         uint32_t b0, uint32_t b1) {
    asm volatile(
        "mma.sync.aligned.m16n8k8.row.col.f32.tf32.tf32.f32 "
        "{%0,%1,%2,%3}, {%4,%5,%6,%7}, {%8,%9}, {%0,%1,%2,%3};"
        : "+f"(d[0]), "+f"(d[1]), "+f"(d[2]), "+f"(d[3])
        : "r"(a[0]), "r"(a[1]), "r"(a[2]), "r"(a[3]), "r"(b0), "r"(b1));
}

// fp16 m16n8k16 with fp32 accumulate
__device__ __forceinline__ void mma_f16(float* d, const uint32_t* a,
                                        uint32_t b0, uint32_t b1) {
    asm volatile(
        "mma.sync.aligned.m16n8k16.row.col.f32.f16.f16.f32 "
        "{%0,%1,%2,%3}, {%4,%5,%6,%7}, {%8,%9}, {%0,%1,%2,%3};"
        : "+f"(d[0]), "+f"(d[1]), "+f"(d[2]), "+f"(d[3])
        : "r"(a[0]), "r"(a[1]), "r"(a[2]), "r"(a[3]), "r"(b0), "r"(b1));
}

// ---------------------------------------------------------------------------
// Kernel 1: QKV projection via mma.sync tf32; outputs fp16.
// Grid (128 row-tiles, 3 chunks). chunk 0 -> Q (scaled), 1 -> K, 2 -> V^T.
// ---------------------------------------------------------------------------
#define QO_W 16384
#define QO_B 32768
#define SMEM_QKV ((32768 + 128) * 4)

__global__ __launch_bounds__(256, 1) void qkv_mma(const float* __restrict__ X,
                                                  const float* __restrict__ W,
                                                  const float* __restrict__ bias)
{
    extern __shared__ float sm[];
    float* Xs = sm;
    float* Ws = sm + QO_W;
    float* Bs = sm + QO_B;

    const int tid = threadIdx.x;
    const int wid = tid >> 5;
    const int lane = tid & 31;
    const int g = lane >> 2;
    const int tg = lane & 3;
    const int xg = g << 2;
    const int m0 = (wid >> 1) * 32;
    const int n0 = (wid & 1) * 64;
    const int row0 = blockIdx.x * 128;
    const int c = blockIdx.y;

    {
        const float4* Xg = (const float4*)(X + (size_t)row0 * HH);
        #pragma unroll
        for (int i = 0; i < 16; i++) {
            int idx = tid + i * 256;
            int r = idx >> 5;
            int c4 = (idx & 31) << 2;
            float4 v = Xg[idx];
            v.x = to_tf32(v.x); v.y = to_tf32(v.y);
            v.z = to_tf32(v.z); v.w = to_tf32(v.w);
            *(float4*)(Xs + (r << 7) + (c4 ^ ((r & 7) << 2))) = v;
        }
        const float4* Wg = (const float4*)(W + (size_t)c * 128 * HH);
        #pragma unroll
        for (int i = 0; i < 16; i++) {
            int idx = tid + i * 256;
            int r = idx >> 5;
            int c4 = (idx & 31) << 2;
            float4 v = Wg[idx];
            v.x = to_tf32(v.x); v.y = to_tf32(v.y);
            v.z = to_tf32(v.z); v.w = to_tf32(v.w);
            *(float4*)(Ws + (r << 7) + (c4 ^ ((r & 7) << 2))) = v;
        }
        if (tid < 128) Bs[tid] = bias[c * 128 + tid];
    }
    __syncthreads();

    float acc[2][8][4];
    #pragma unroll
    for (int st = 0; st < 2; st++)
        #pragma unroll
        for (int nt = 0; nt < 8; nt++)
            #pragma unroll
            for (int j = 0; j < 4; j++) acc[st][nt][j] = 0.0f;

    const float* XA0 = Xs + ((m0 + g) << 7);
    const float* XA1 = Xs + ((m0 + 8 + g) << 7);
    const float* XA2 = Xs + ((m0 + 16 + g) << 7);
    const float* XA3 = Xs + ((m0 + 24 + g) << 7);

    #pragma unroll 2
    for (int ks = 0; ks < 16; ks++) {
        const int k0 = ks * 8;
        const int c0 = (k0 + tg) ^ xg;
        const int c1 = (k0 + tg + 4) ^ xg;
        uint32_t a0[4], a1[4];
        a0[0] = __float_as_uint(XA0[c0]);
        a0[1] = __float_as_uint(XA1[c0]);
        a0[2] = __float_as_uint(XA0[c1]);
        a0[3] = __float_as_uint(XA1[c1]);
        a1[0] = __float_as_uint(XA2[c0]);
        a1[1] = __float_as_uint(XA3[c0]);
        a1[2] = __float_as_uint(XA2[c1]);
        a1[3] = __float_as_uint(XA3[c1]);
        #pragma unroll
        for (int nt = 0; nt < 8; nt++) {
            const float* Br = Ws + ((n0 + nt * 8 + g) << 7);
            uint32_t b0 = __float_as_uint(Br[c0]);
            uint32_t b1 = __float_as_uint(Br[c1]);
            mma_tf32(acc[0][nt], a0, b0, b1);
            mma_tf32(acc[1][nt], a1, b0, b1);
        }
    }

    if (c == 2) {
        __syncthreads();
        float* St = sm;    // 128 x 130 plain (s rows, h cols)
        #pragma unroll
        for (int st = 0; st < 2; st++) {
            #pragma unroll
            for (int nt = 0; nt < 8; nt++) {
                int col = n0 + nt * 8 + 2 * tg;
                int r0 = m0 + 16 * st + g;
                int r1 = r0 + 8;
                float b0v = Bs[col], b1v = Bs[col + 1];
                St[r0 * 130 + col]     = acc[st][nt][0] + b0v;
                St[r0 * 130 + col + 1] = acc[st][nt][1] + b1v;
                St[r1 * 130 + col]     = acc[st][nt][2] + b0v;
                St[r1 * 130 + col + 1] = acc[st][nt][3] + b1v;
            }
        }
        __syncthreads();
        const int b = row0 >> 12;
        const int sbase = row0 & 4095;
        #pragma unroll 4
        for (int i = 0; i < 64; i++) {
            int idx = tid + i * 256;
            int h = idx >> 7;
            int s = idx & 127;
            g_Vt[((size_t)(b * HH + h)) * SS + sbase + s] = __float2half_rn(St[s * 130 + h]);
        }
    } else {
        __half* dst = (c == 0 ? g_Q : g_K) + (size_t)row0 * HH;
        const float scale = (c == 0) ? 0.08838834764831845f : 1.0f;
        #pragma unroll
        for (int st = 0; st < 2; st++) {
            #pragma unroll
            for (int nt = 0; nt < 8; nt++) {
                int col = n0 + nt * 8 + 2 * tg;
                int r0 = m0 + 16 * st + g;
                int r1 = r0 + 8;
                float b0v = Bs[col], b1v = Bs[col + 1];
                *(__half2*)(dst + (size_t)r0 * HH + col) =
                    __floats2half2_rn((acc[st][nt][0] + b0v) * scale,
                                      (acc[st][nt][1] + b1v) * scale);
                *(__half2*)(dst + (size_t)r1 * HH + col) =
                    __floats2half2_rn((acc[st][nt][2] + b0v) * scale,
                                      (acc[st][nt][3] + b1v) * scale);
            }
        }
    }
}

// ---------------------------------------------------------------------------
// Kernel 2: flash attention, fp16 mma.sync m16n8k16, 512 threads (16 warps).
// Warp w: m-strip (w>>2)*32, n-quarter w&3 (S: 32 keys, PV: 32 head dims).
// Key-tile 128, cp.async double-buffered. Per-strip named barrier (128 thr).
// SMEM tiles stored as u32 (=half2), 64 u32/row, swizzle: col ^ 4*(row&7).
// Layout (u32): Q[8192] K0[8192] K1[8192] V0[8192] V1[8192] P[8192] = 192KB.
// ---------------------------------------------------------------------------
#define UQ  0
#define UK0 8192
#define UK1 16384
#define UV0 24576
#define UV1 32768
#define UP  40960
#define SMEM_ATTN (49152 * 4)   // 196608 B

__global__ __launch_bounds__(512, 1) void attn_kernel(float* __restrict__ out)
{
    extern __shared__ uint32_t smu[];
    const uint32_t smem_u32 = smem_u32_of(smu);

    const int tid = threadIdx.x;
    const int wid = tid >> 5;
    const int lane = tid & 31;
    const int g = lane >> 2;
    const int tg = lane & 3;
    const int xg = g << 2;
    const int m0 = (wid >> 2) * 32;       // m-strip base (4 strips)
    const int nq = wid & 3;               // n-quarter
    const int n0k = nq * 32;              // S: 32 keys per warp
    const int n0p = nq * 32;              // PV: 32 head dims per warp
    const int strip_bar = 1 + (wid >> 2); // named barrier per strip (128 thr)
    const int b = blockIdx.y;
    const int q0 = blockIdx.x * 128;

    // ---- prologue: stage tile 0 (K,V fp16: 128 rows x 16 16B-chunks each) ----
    {
        const __half* Kg = g_K + ((size_t)b * SS) * HH;
        const __half* Vg = g_Vt + (size_t)(b * HH) * SS;
        #pragma unroll
        for (int i = 0; i < 4; i++) {
            int idx = tid + i * 512;
            int r = idx >> 4;
            int c4 = (idx & 15) << 2;
            int sw = c4 ^ ((r & 7) << 2);
            cp_async16(smem_u32 + (UK0 + r * 64 + sw) * 4, Kg + r * HH + c4 * 2);
            cp_async16(smem_u32 + (UV0 + r * 64 + sw) * 4, Vg + (size_t)r * SS + c4 * 2);
        }
        CP_COMMIT();
        // Q tile
        const __half* Qg = g_Q + ((size_t)b * SS + q0) * HH;
        #pragma unroll
        for (int i = 0; i < 4; i++) {
            int idx = tid + i * 512;
            int r = idx >> 4;
            int c4 = (idx & 15) << 2;
            int sw = c4 ^ ((r & 7) << 2);
            *(uint4*)(smu + UQ + r * 64 + sw) = *(const uint4*)(Qg + r * HH + c4 * 2);
        }
    }

    float oacc[2][4][4];
    #pragma unroll
    for (int st = 0; st < 2; st++)
        #pragma unroll
        for (int nt = 0; nt < 4; nt++)
            #pragma unroll
            for (int j = 0; j < 4; j++) oacc[st][nt][j] = 0.0f;
    float lsum[4] = {0.0f, 0.0f, 0.0f, 0.0f};

    // Fragment row pointers (all rows == g mod 8 -> swizzle xor = xg)
    const uint32_t* QA0 = smu + UQ + (m0 + g) * 64;
    const uint32_t* QA1 = smu + UQ + (m0 + 8 + g) * 64;
    const uint32_t* QA2 = smu + UQ + (m0 + 16 + g) * 64;
    const uint32_t* QA3 = smu + UQ + (m0 + 24 + g) * 64;
    uint32_t* PW0 = smu + UP + (m0 + g) * 64;
    uint32_t* PW1 = smu + UP + (m0 + 8 + g) * 64;
    uint32_t* PW2 = smu + UP + (m0 + 16 + g) * 64;
    uint32_t* PW3 = smu + UP + (m0 + 24 + g) * 64;

    for (int t = 0; t < 32; t++) {
        const int buf = t & 1;
        const uint32_t* Kb = smu + (buf ? UK1 : UK0);
        const uint32_t* Vb = smu + (buf ? UV1 : UV0);

        CP_WAIT0();
        __syncthreads();   // tile t visible; tile t-1 reads fully retired

        // Prefetch tile t+1
        if (t + 1 < 32) {
            const int ok = buf ? UK0 : UK1;
            const int ov = buf ? UV0 : UV1;
            const __half* Kg = g_K + ((size_t)b * SS + (t + 1) * 128) * HH;
            const __half* Vg = g_Vt + (size_t)(b * HH) * SS + (t + 1) * 128;
            #pragma unroll
            for (int i = 0; i < 4; i++) {
                int idx = tid + i * 512;
                int r = idx >> 4;
                int c4 = (idx & 15) << 2;
                int sw = c4 ^ ((r & 7) << 2);
                cp_async16(smem_u32 + (ok + r * 64 + sw) * 4, Kg + r * HH + c4 * 2);
                cp_async16(smem_u32 + (ov + r * 64 + sw) * 4, Vg + (size_t)r * SS + c4 * 2);
            }
            CP_COMMIT();
        }

        // --- S = Q . K^T : warp tile m32 x n32 x k128 (fp16, k16/step) ---
        float sacc[2][4][4];
        #pragma unroll
        for (int st = 0; st < 2; st++)
            #pragma unroll
            for (int nt = 0; nt < 4; nt++)
                #pragma unroll
                for (int j = 0; j < 4; j++) sacc[st][nt][j] = 0.0f;

        #pragma unroll 2
        for (int ks = 0; ks < 8; ks++) {
            const int c0 = (ks * 8 + tg) ^ xg;
            const int c1 = (ks * 8 + tg + 4) ^ xg;
            uint32_t a0[4], a1[4];
            a0[0] = QA0[c0]; a0[1] = QA1[c0]; a0[2] = QA0[c1]; a0[3] = QA1[c1];
            a1[0] = QA2[c0]; a1[1] = QA3[c0]; a1[2] = QA2[c1]; a1[3] = QA3[c1];
            #pragma unroll
            for (int nt = 0; nt < 4; nt++) {
                const uint32_t* Br = Kb + (n0k + nt * 8 + g) * 64;
                uint32_t b0 = Br[c0];
                uint32_t b1 = Br[c1];
                mma_f16(sacc[0][nt], a0, b0, b1);
                mma_f16(sacc[1][nt], a1, b0, b1);
            }
        }

        // --- exp + partial row sums + write P (fp16 pairs, swizzled) ---
        {
            float ps0 = 0.0f, ps1 = 0.0f, ps2 = 0.0f, ps3 = 0.0f;
            #pragma unroll
            for (int nt = 0; nt < 4; nt++) {
                int cp = (nq * 16 + nt * 4 + tg) ^ xg;
                float e0 = __expf(sacc[0][nt][0]);
                float e1 = __expf(sacc[0][nt][1]);
                float e2 = __expf(sacc[0][nt][2]);
                float e3 = __expf(sacc[0][nt][3]);
                ps0 += e0 + e1; ps1 += e2 + e3;
                __half2 h01 = __floats2half2_rn(e0, e1);
                __half2 h23 = __floats2half2_rn(e2, e3);
                PW0[cp] = *reinterpret_cast<uint32_t*>(&h01);
                PW1[cp] = *reinterpret_cast<uint32_t*>(&h23);
                float f0 = __expf(sacc[1][nt][0]);
                float f1 = __expf(sacc[1][nt][1]);
                float f2 = __expf(sacc[1][nt][2]);
                float f3 = __expf(sacc[1][nt][3]);
                ps2 += f0 + f1; ps3 += f2 + f3;
                __half2 g01 = __floats2half2_rn(f0, f1);
                __half2 g23 = __floats2half2_rn(f2, f3);
                PW2[cp] = *reinterpret_cast<uint32_t*>(&g01);
                PW3[cp] = *reinterpret_cast<uint32_t*>(&g23);
            }
            ps0 += __shfl_xor_sync(0xffffffffu, ps0, 1);
            ps0 += __shfl_xor_sync(0xffffffffu, ps0, 2);
            ps1 += __shfl_xor_sync(0xffffffffu, ps1, 1);
            ps1 += __shfl_xor_sync(0xffffffffu, ps1, 2);
            ps2 += __shfl_xor_sync(0xffffffffu, ps2, 1);
            ps2 += __shfl_xor_sync(0xffffffffu, ps2, 2);
            ps3 += __shfl_xor_sync(0xffffffffu, ps3, 1);
            ps3 += __shfl_xor_sync(0xffffffffu, ps3, 2);
            lsum[0] += ps0; lsum[1] += ps1; lsum[2] += ps2; lsum[3] += ps3;
        }
        // Strip barrier: 4 warps of this m-strip exchange P rows
        asm volatile("bar.sync %0, 128;" :: "r"(strip_bar) : "memory");

        // --- O += P . V : warp tile m32 x h32 x k128 ---
        #pragma unroll 2
        for (int ks = 0; ks < 8; ks++) {
            const int c0 = (ks * 8 + tg) ^ xg;
            const int c1 = (ks * 8 + tg + 4) ^ xg;
            uint32_t a0[4], a1[4];
            a0[0] = PW0[c0]; a0[1] = PW1[c0]; a0[2] = PW0[c1]; a0[3] = PW1[c1];
            a1[0] = PW2[c0]; a1[1] = PW3[c0]; a1[2] = PW2[c1]; a1[3] = PW3[c1];
            #pragma unroll
            for (int nt = 0; nt < 4; nt++) {
                const uint32_t* Br = Vb + (n0p + nt * 8 + g) * 64;
                uint32_t b0 = Br[c0];
                uint32_t b1 = Br[c1];
                mma_f16(oacc[0][nt], a0, b0, b1);
                mma_f16(oacc[1][nt], a1, b0, b1);
            }
        }
    }

    // --- Combine per-quarter row sums via smem (reuse P region as f32) ---
    __syncthreads();
    {
        float* LS = (float*)(smu + UP) + nq * 128;
        if (tg == 0) {
            LS[m0 + g] = lsum[0];
            LS[m0 + 8 + g] = lsum[1];
            LS[m0 + 16 + g] = lsum[2];
            LS[m0 + 24 + g] = lsum[3];
        }
    }
    __syncthreads();

    // --- Epilogue: O / l -> gmem (f32 out) ---
    {
        const float* LS = (const float*)(smu + UP);
        float* og = out + ((size_t)(b * SS) + q0) * HH + n0p;
        #pragma unroll
        for (int st = 0; st < 2; st++) {
            int r0 = m0 + 16 * st + g;
            int r1 = r0 + 8;
            float inv0 = 1.0f / (LS[r0] + LS[128 + r0] + LS[256 + r0] + LS[384 + r0]);
            float inv1 = 1.0f / (LS[r1] + LS[128 + r1] + LS[256 + r1] + LS[384 + r1]);
            float* o0 = og + (size_t)r0 * HH;
            float* o1 = og + (size_t)r1 * HH;
            #pragma unroll
            for (int nt = 0; nt < 4; nt++) {
                int col = nt * 8 + 2 * tg;
                *(float2*)(o0 + col) =
                    make_float2(oacc[st][nt][0] * inv0, oacc[st][nt][1] * inv0);
                *(float2*)(o1 + col) =
                    make_float2(oacc[st][nt][2] * inv1, oacc[st][nt][3] * inv1);
            }
        }
    }
}

// ---------------------------------------------------------------------------
extern "C" void kernel_launch(void* const* d_in, const int* in_sizes, int n_in,
                              void* d_out, int out_size)
{
    const float* X    = (const float*)d_in[0];   // [4,4096,128]
    const float* W    = (const float*)d_in[1];   // [384,128]
    const float* bias = (const float*)d_in[2];   // [384]
    float* out = (float*)d_out;                  // [4,4096,128]

    cudaFuncSetAttribute(qkv_mma, cudaFuncAttributeMaxDynamicSharedMemorySize, SMEM_QKV);
    cudaFuncSetAttribute(attn_kernel, cudaFuncAttributeMaxDynamicSharedMemorySize, SMEM_ATTN);

    qkv_mma<<<dim3(128, 3), 256, SMEM_QKV>>>(X, W, bias);
    attn_kernel<<<dim3(SS / 128, BB), 512, SMEM_ATTN>>>(out);
}